// round 2
// baseline (speedup 1.0000x reference)
#include <cuda_runtime.h>
#include <cuda_bf16.h>
#include <math.h>

// Problem dims (fixed by the dataset)
#define BATCH 32
#define PTOK  256
#define DIM   2048
#define HID   8192
#define NVIEW 3
#define ROWS  (BATCH * PTOK)   // 8192

// Scratch (static device allocations — no cudaMalloc allowed)
__device__ int   g_idx[BATCH];
__device__ float g_xn[(size_t)ROWS * DIM];     // 67 MB  normalized input
__device__ float g_h [(size_t)ROWS * HID];     // 268 MB hidden activations

// ---------------------------------------------------------------------------
// Decode view indices: dataset reference declares int64, but JAX without x64
// canonicalizes to int32. Detect at runtime: int64 layout iff every pair
// (lo in [0,NVIEW), hi == 0) holds for all 32 entries.
// ---------------------------------------------------------------------------
__global__ void decode_idx_kernel(const int* __restrict__ p) {
    bool is64 = true;
    for (int b = 0; b < BATCH; b++) {
        int lo = p[2 * b];
        int hi = p[2 * b + 1];
        if (!(lo >= 0 && lo < NVIEW && hi == 0)) { is64 = false; break; }
    }
    for (int b = 0; b < BATCH; b++) {
        g_idx[b] = is64 ? p[2 * b] : p[b];
    }
}

// ---------------------------------------------------------------------------
// LayerNorm over D=2048, per-row. 256 threads/block, 8 elems/thread.
// ---------------------------------------------------------------------------
__global__ void __launch_bounds__(256) ln_kernel(
    const float* __restrict__ x,
    const float* __restrict__ gamma,
    const float* __restrict__ beta)
{
    const int row    = blockIdx.x;            // 0..8191
    const int sample = row >> 8;              // row / 256
    const int view   = g_idx[sample];
    const float* xr  = x + (size_t)row * DIM;

    const int tid = threadIdx.x;

    float4 v0 = *(const float4*)(xr + tid * 4);
    float4 v1 = *(const float4*)(xr + 1024 + tid * 4);

    float s  = v0.x + v0.y + v0.z + v0.w + v1.x + v1.y + v1.z + v1.w;
    float ss = v0.x*v0.x + v0.y*v0.y + v0.z*v0.z + v0.w*v0.w
             + v1.x*v1.x + v1.y*v1.y + v1.z*v1.z + v1.w*v1.w;

    // warp reduce
    #pragma unroll
    for (int off = 16; off > 0; off >>= 1) {
        s  += __shfl_xor_sync(0xffffffffu, s,  off);
        ss += __shfl_xor_sync(0xffffffffu, ss, off);
    }
    __shared__ float red_s[8], red_ss[8];
    const int wid  = tid >> 5;
    const int lane = tid & 31;
    if (lane == 0) { red_s[wid] = s; red_ss[wid] = ss; }
    __syncthreads();
    if (wid == 0) {
        float a = (lane < 8) ? red_s[lane]  : 0.f;
        float b = (lane < 8) ? red_ss[lane] : 0.f;
        #pragma unroll
        for (int off = 4; off > 0; off >>= 1) {
            a += __shfl_xor_sync(0xffffffffu, a, off);
            b += __shfl_xor_sync(0xffffffffu, b, off);
        }
        if (lane == 0) { red_s[0] = a; red_ss[0] = b; }
    }
    __syncthreads();
    const float mean = red_s[0]  * (1.0f / DIM);
    const float var  = red_ss[0] * (1.0f / DIM) - mean * mean;
    const float inv  = rsqrtf(var + 1e-5f);

    const float* g = gamma + (size_t)view * DIM;
    const float* b = beta  + (size_t)view * DIM;
    float* out = g_xn + (size_t)row * DIM;

    int c0 = tid * 4;
    float4 o0, o1;
    o0.x = (v0.x - mean) * inv * g[c0+0] + b[c0+0];
    o0.y = (v0.y - mean) * inv * g[c0+1] + b[c0+1];
    o0.z = (v0.z - mean) * inv * g[c0+2] + b[c0+2];
    o0.w = (v0.w - mean) * inv * g[c0+3] + b[c0+3];
    int c1 = 1024 + tid * 4;
    o1.x = (v1.x - mean) * inv * g[c1+0] + b[c1+0];
    o1.y = (v1.y - mean) * inv * g[c1+1] + b[c1+1];
    o1.z = (v1.z - mean) * inv * g[c1+2] + b[c1+2];
    o1.w = (v1.w - mean) * inv * g[c1+3] + b[c1+3];
    *(float4*)(out + c0) = o0;
    *(float4*)(out + c1) = o1;
}

// ---------------------------------------------------------------------------
// GEMM1: h = GELU(xn @ W1[view] + b1[view])
//   A = g_xn [8192, 2048], B = W1[view] [2048, 8192] row-major (k-major rows)
//   Tiling: 128x128x16, 256 threads, 8x8 per thread (4+4 split layout).
// ---------------------------------------------------------------------------
__global__ void __launch_bounds__(256) gemm1_kernel(
    const float* __restrict__ W1,
    const float* __restrict__ b1)
{
    const int nb = blockIdx.x;          // 0..63 (N tiles of 8192)
    const int mb = blockIdx.y;          // 0..63 (M tiles of 8192)
    const int sample = mb >> 1;         // 2 M-tiles per sample (256 rows)
    const int view = g_idx[sample];

    const float* A  = g_xn + (size_t)mb * 128 * DIM;
    const float* Bm = W1 + (size_t)view * DIM * HID + (size_t)nb * 128;

    __shared__ float As[16][132];       // transposed A tile, padded
    __shared__ float Bs[16][128];

    const int tid = threadIdx.x;
    const int tx = tid & 15;
    const int ty = tid >> 4;

    float acc[8][8];
    #pragma unroll
    for (int i = 0; i < 8; i++)
        #pragma unroll
        for (int j = 0; j < 8; j++) acc[i][j] = 0.f;

    for (int k0 = 0; k0 < DIM; k0 += 16) {
        // A tile: 128 rows x 16 k (coalesced, stored transposed)
        #pragma unroll
        for (int i = 0; i < 2; i++) {
            int t = tid + i * 256;
            int row = t >> 2;
            int kq  = (t & 3) << 2;
            float4 v = *(const float4*)(A + (size_t)row * DIM + k0 + kq);
            As[kq+0][row] = v.x;
            As[kq+1][row] = v.y;
            As[kq+2][row] = v.z;
            As[kq+3][row] = v.w;
        }
        // B tile: 16 k x 128 n (coalesced)
        #pragma unroll
        for (int i = 0; i < 2; i++) {
            int t = tid + i * 256;
            int kr = t >> 5;
            int nc = (t & 31) << 2;
            *(float4*)(&Bs[kr][nc]) =
                *(const float4*)(Bm + (size_t)(k0 + kr) * HID + nc);
        }
        __syncthreads();

        #pragma unroll
        for (int kk = 0; kk < 16; kk++) {
            float af[8], bf[8];
            *(float4*)&af[0] = *(const float4*)&As[kk][ty * 4];
            *(float4*)&af[4] = *(const float4*)&As[kk][64 + ty * 4];
            *(float4*)&bf[0] = *(const float4*)&Bs[kk][tx * 4];
            *(float4*)&bf[4] = *(const float4*)&Bs[kk][64 + tx * 4];
            #pragma unroll
            for (int i = 0; i < 8; i++)
                #pragma unroll
                for (int j = 0; j < 8; j++)
                    acc[i][j] += af[i] * bf[j];
        }
        __syncthreads();
    }

    // epilogue: bias + exact GELU -> g_h
    const int grow = mb * 128;
    const int gcol = nb * 128;
    #pragma unroll
    for (int i = 0; i < 8; i++) {
        int m = (i < 4) ? (ty * 4 + i) : (64 + ty * 4 + (i - 4));
        size_t rowoff = (size_t)(grow + m) * HID + gcol;
        #pragma unroll
        for (int j = 0; j < 8; j++) {
            int n = (j < 4) ? (tx * 4 + j) : (64 + tx * 4 + (j - 4));
            float v = acc[i][j] + b1[(size_t)view * HID + gcol + n];
            v = 0.5f * v * (1.0f + erff(v * 0.70710678118654752f));
            g_h[rowoff + n] = v;
        }
    }
}

// ---------------------------------------------------------------------------
// GEMM2: out = x + h @ W2[view] + b2[view]
//   A = g_h [8192, 8192], B = W2[view] [8192, 2048] row-major
// ---------------------------------------------------------------------------
__global__ void __launch_bounds__(256) gemm2_kernel(
    const float* __restrict__ W2,
    const float* __restrict__ b2,
    const float* __restrict__ x,
    float* __restrict__ out)
{
    const int nb = blockIdx.x;          // 0..15 (N tiles of 2048)
    const int mb = blockIdx.y;          // 0..63
    const int sample = mb >> 1;
    const int view = g_idx[sample];

    const float* A  = g_h + (size_t)mb * 128 * HID;
    const float* Bm = W2 + (size_t)view * HID * DIM + (size_t)nb * 128;

    __shared__ float As[16][132];
    __shared__ float Bs[16][128];

    const int tid = threadIdx.x;
    const int tx = tid & 15;
    const int ty = tid >> 4;

    float acc[8][8];
    #pragma unroll
    for (int i = 0; i < 8; i++)
        #pragma unroll
        for (int j = 0; j < 8; j++) acc[i][j] = 0.f;

    for (int k0 = 0; k0 < HID; k0 += 16) {
        #pragma unroll
        for (int i = 0; i < 2; i++) {
            int t = tid + i * 256;
            int row = t >> 2;
            int kq  = (t & 3) << 2;
            float4 v = *(const float4*)(A + (size_t)row * HID + k0 + kq);
            As[kq+0][row] = v.x;
            As[kq+1][row] = v.y;
            As[kq+2][row] = v.z;
            As[kq+3][row] = v.w;
        }
        #pragma unroll
        for (int i = 0; i < 2; i++) {
            int t = tid + i * 256;
            int kr = t >> 5;
            int nc = (t & 31) << 2;
            *(float4*)(&Bs[kr][nc]) =
                *(const float4*)(Bm + (size_t)(k0 + kr) * DIM + nc);
        }
        __syncthreads();

        #pragma unroll
        for (int kk = 0; kk < 16; kk++) {
            float af[8], bf[8];
            *(float4*)&af[0] = *(const float4*)&As[kk][ty * 4];
            *(float4*)&af[4] = *(const float4*)&As[kk][64 + ty * 4];
            *(float4*)&bf[0] = *(const float4*)&Bs[kk][tx * 4];
            *(float4*)&bf[4] = *(const float4*)&Bs[kk][64 + tx * 4];
            #pragma unroll
            for (int i = 0; i < 8; i++)
                #pragma unroll
                for (int j = 0; j < 8; j++)
                    acc[i][j] += af[i] * bf[j];
        }
        __syncthreads();
    }

    const int grow = mb * 128;
    const int gcol = nb * 128;
    #pragma unroll
    for (int i = 0; i < 8; i++) {
        int m = (i < 4) ? (ty * 4 + i) : (64 + ty * 4 + (i - 4));
        size_t rowoff = (size_t)(grow + m) * DIM + gcol;
        #pragma unroll
        for (int j = 0; j < 8; j++) {
            int n = (j < 4) ? (tx * 4 + j) : (64 + tx * 4 + (j - 4));
            float v = acc[i][j] + b2[(size_t)view * DIM + gcol + n];
            out[rowoff + n] = x[rowoff + n] + v;
        }
    }
}

// ---------------------------------------------------------------------------
// Launch
// ---------------------------------------------------------------------------
extern "C" void kernel_launch(void* const* d_in, const int* in_sizes, int n_in,
                              void* d_out, int out_size) {
    const float* x     = (const float*)d_in[0];   // [32,256,2048]
    const int*   idx   = (const int*)  d_in[1];   // [32] int32 or int64
    const float* gamma = (const float*)d_in[2];   // [3,2048]
    const float* beta  = (const float*)d_in[3];   // [3,2048]
    const float* W1    = (const float*)d_in[4];   // [3,2048,8192]
    const float* b1    = (const float*)d_in[5];   // [3,8192]
    const float* W2    = (const float*)d_in[6];   // [3,8192,2048]
    const float* b2    = (const float*)d_in[7];   // [3,2048]
    float* out = (float*)d_out;                   // [32,256,2048]

    decode_idx_kernel<<<1, 1>>>(idx);
    ln_kernel<<<ROWS, 256>>>(x, gamma, beta);
    gemm1_kernel<<<dim3(HID / 128, ROWS / 128), 256>>>(W1, b1);
    gemm2_kernel<<<dim3(DIM / 128, ROWS / 128), 256>>>(W2, b2, x, out);
}

// round 6
// speedup vs baseline: 1.7604x; 1.7604x over previous
#include <cuda_runtime.h>
#include <cuda_bf16.h>
#include <math.h>
#include <stdint.h>

// Problem dims
#define BATCH 32
#define PTOK  256
#define DIM   2048
#define HID   8192
#define NVIEW 3
#define ROWS  (BATCH * PTOK)   // 8192

// ---------------------------------------------------------------------------
// Device scratch (static; no cudaMalloc allowed)
// ---------------------------------------------------------------------------
__device__ int g_idx[BATCH];
__device__ int g_morder[ROWS / 128];   // M-tiles sorted by view

__device__ __nv_bfloat16 g_xah[(size_t)ROWS * DIM];
__device__ __nv_bfloat16 g_xal[(size_t)ROWS * DIM];
__device__ __nv_bfloat16 g_hh [(size_t)ROWS * HID];
__device__ __nv_bfloat16 g_hl [(size_t)ROWS * HID];
__device__ __nv_bfloat16 g_w1h[(size_t)NVIEW * HID * DIM];  // [v][n=HID][k=DIM]
__device__ __nv_bfloat16 g_w1l[(size_t)NVIEW * HID * DIM];
__device__ __nv_bfloat16 g_w2h[(size_t)NVIEW * DIM * HID];  // [v][n=DIM][k=HID]
__device__ __nv_bfloat16 g_w2l[(size_t)NVIEW * DIM * HID];

// ---------------------------------------------------------------------------
// PTX helpers (base sm_103-safe: mma.sync / ldmatrix / cp.async only)
// ---------------------------------------------------------------------------
__device__ __forceinline__ uint32_t smem_u32(const void* p) {
    uint32_t a;
    asm("{ .reg .u64 t; cvta.to.shared.u64 t, %1; cvt.u32.u64 %0, t; }"
        : "=r"(a) : "l"(p));
    return a;
}

__device__ __forceinline__ void cp16(uint32_t dst, const void* src) {
    asm volatile("cp.async.cg.shared.global [%0], [%1], 16;" :: "r"(dst), "l"(src));
}
#define CP_COMMIT() asm volatile("cp.async.commit_group;" ::: "memory")
#define CP_WAIT(n)  asm volatile("cp.async.wait_group %0;" :: "n"(n) : "memory")

__device__ __forceinline__ void ldm4(uint32_t* r, uint32_t a) {
    asm volatile("ldmatrix.sync.aligned.m8n8.x4.shared.b16 {%0,%1,%2,%3}, [%4];"
        : "=r"(r[0]), "=r"(r[1]), "=r"(r[2]), "=r"(r[3]) : "r"(a));
}

__device__ __forceinline__ void mma16816(float* c, const uint32_t* a, const uint32_t* b) {
    asm volatile(
        "mma.sync.aligned.m16n8k16.row.col.f32.bf16.bf16.f32 "
        "{%0,%1,%2,%3}, {%4,%5,%6,%7}, {%8,%9}, {%0,%1,%2,%3};"
        : "+f"(c[0]), "+f"(c[1]), "+f"(c[2]), "+f"(c[3])
        : "r"(a[0]), "r"(a[1]), "r"(a[2]), "r"(a[3]), "r"(b[0]), "r"(b[1]));
}

// ---------------------------------------------------------------------------
// decode idx + build view-sorted M-tile order
// ---------------------------------------------------------------------------
__global__ void decode_idx_kernel(const int* __restrict__ p) {
    bool is64 = true;
    for (int b = 0; b < BATCH; b++) {
        int lo = p[2 * b], hi = p[2 * b + 1];
        if (!(lo >= 0 && lo < NVIEW && hi == 0)) { is64 = false; break; }
    }
    for (int b = 0; b < BATCH; b++) g_idx[b] = is64 ? p[2 * b] : p[b];
    int c = 0;
    for (int v = 0; v < NVIEW; v++)
        for (int s = 0; s < BATCH; s++)
            if (g_idx[s] == v) { g_morder[c++] = 2 * s; g_morder[c++] = 2 * s + 1; }
}

// ---------------------------------------------------------------------------
// LayerNorm -> bf16 hi/lo planes
// ---------------------------------------------------------------------------
__global__ void __launch_bounds__(256) ln_kernel(
    const float* __restrict__ x,
    const float* __restrict__ gamma,
    const float* __restrict__ beta)
{
    const int row = blockIdx.x;
    const int view = g_idx[row >> 8];
    const float* xr = x + (size_t)row * DIM;
    const int tid = threadIdx.x;

    float4 v0 = *(const float4*)(xr + tid * 4);
    float4 v1 = *(const float4*)(xr + 1024 + tid * 4);

    float s  = v0.x + v0.y + v0.z + v0.w + v1.x + v1.y + v1.z + v1.w;
    float ss = v0.x*v0.x + v0.y*v0.y + v0.z*v0.z + v0.w*v0.w
             + v1.x*v1.x + v1.y*v1.y + v1.z*v1.z + v1.w*v1.w;
    #pragma unroll
    for (int off = 16; off > 0; off >>= 1) {
        s  += __shfl_xor_sync(0xffffffffu, s,  off);
        ss += __shfl_xor_sync(0xffffffffu, ss, off);
    }
    __shared__ float rs[8], rss[8];
    int wid = tid >> 5, lane = tid & 31;
    if (lane == 0) { rs[wid] = s; rss[wid] = ss; }
    __syncthreads();
    if (wid == 0) {
        float a = (lane < 8) ? rs[lane] : 0.f;
        float b = (lane < 8) ? rss[lane] : 0.f;
        #pragma unroll
        for (int off = 4; off > 0; off >>= 1) {
            a += __shfl_xor_sync(0xffffffffu, a, off);
            b += __shfl_xor_sync(0xffffffffu, b, off);
        }
        if (lane == 0) { rs[0] = a; rss[0] = b; }
    }
    __syncthreads();
    const float mean = rs[0] * (1.0f / DIM);
    const float var  = rss[0] * (1.0f / DIM) - mean * mean;
    const float inv  = rsqrtf(var + 1e-5f);

    const float* g = gamma + (size_t)view * DIM;
    const float* b = beta  + (size_t)view * DIM;
    size_t base = (size_t)row * DIM;

    float v[8];
    v[0]=v0.x; v[1]=v0.y; v[2]=v0.z; v[3]=v0.w; v[4]=v1.x; v[5]=v1.y; v[6]=v1.z; v[7]=v1.w;
    #pragma unroll
    for (int j = 0; j < 8; j++) {
        int c = (j < 4) ? (tid * 4 + j) : (1024 + tid * 4 + (j - 4));
        float o = (v[j] - mean) * inv * g[c] + b[c];
        __nv_bfloat16 hi = __float2bfloat16(o);
        __nv_bfloat16 lo = __float2bfloat16(o - __bfloat162float(hi));
        g_xah[base + c] = hi;
        g_xal[base + c] = lo;
    }
}

// ---------------------------------------------------------------------------
// Weight transpose + bf16 split: W [v][K][N] fp32 -> out [v][N][K] hi/lo bf16
// ---------------------------------------------------------------------------
__global__ void __launch_bounds__(256) wt_kernel(
    const float* __restrict__ W,
    __nv_bfloat16* __restrict__ oh,
    __nv_bfloat16* __restrict__ ol,
    int K, int N)
{
    __shared__ float t[32][33];
    int n0 = blockIdx.x * 32, k0 = blockIdx.y * 32, v = blockIdx.z;
    int tx = threadIdx.x, ty = threadIdx.y;
    const float* src = W + ((size_t)v * K + k0) * N + n0;
    #pragma unroll
    for (int i = 0; i < 4; i++)
        t[ty + 8 * i][tx] = src[(size_t)(ty + 8 * i) * N + tx];
    __syncthreads();
    #pragma unroll
    for (int i = 0; i < 4; i++) {
        float val = t[tx][ty + 8 * i];
        __nv_bfloat16 hi = __float2bfloat16(val);
        __nv_bfloat16 lo = __float2bfloat16(val - __bfloat162float(hi));
        size_t o = ((size_t)v * N + n0 + ty + 8 * i) * K + k0 + tx;
        oh[o] = hi;
        ol[o] = lo;
    }
}

// ---------------------------------------------------------------------------
// Warp-MMA GEMM: D[128x128] = A[128xK] @ B[128xK]^T  (bf16 hi/lo split)
// 256 threads = 8 warps in 2(M) x 4(N); warp tile 64x32.
// smem stage: A(2 planes) + B(2 planes), 80B row stride (conflict-free ldmatrix)
// ---------------------------------------------------------------------------
#define RSTR   80                       // smem row stride (bytes), 32 bf16 used
#define PL_SZ  (128 * RSTR)             // 10240 bytes per plane
#define OFF_B  (2 * PL_SZ)              // B planes after A planes
#define STG    (4 * PL_SZ)              // 40960 per stage
#define SMEM_DYN (2 * STG)              // 81920

template<int KTOT, int NTOT, bool GELU>
__global__ void __launch_bounds__(256, 1) gemm_mma(
    const __nv_bfloat16* __restrict__ Ah, const __nv_bfloat16* __restrict__ Al,
    const __nv_bfloat16* __restrict__ Bh, const __nv_bfloat16* __restrict__ Bl,
    const float* __restrict__ bias,
    const float* __restrict__ xres, float* __restrict__ outp,
    __nv_bfloat16* __restrict__ outH, __nv_bfloat16* __restrict__ outL)
{
    constexpr int NS = KTOT / 32;
    extern __shared__ char smem[];
    const uint32_t sbase = smem_u32(smem);
    const int tid = threadIdx.x;
    const int lane = tid & 31;
    const int wrp = tid >> 5;
    const int wm = wrp & 1;          // 0..1 (M)
    const int wn = wrp >> 1;         // 0..3 (N)

    // block mapping: groups of 8 N-tiles x all 64 view-sorted M-tiles
    const int bx = blockIdx.x;
    const int g = bx >> 9, r = bx & 511;
    const int mb = g_morder[r >> 3];
    const int nb = (g << 3) | (r & 7);
    const int view = g_idx[mb >> 1];
    const int grow = mb * 128;
    const size_t arow0 = (size_t)grow;
    const size_t brow0 = (size_t)view * NTOT + (size_t)nb * 128;
    const int gcol = nb * 128;

    const char* pAh = (const char*)Ah;
    const char* pAl = (const char*)Al;
    const char* pBh = (const char*)Bh;
    const char* pBl = (const char*)Bl;

    // ---- stage loader: 128 rows x 32 k x (A,B) x (hi,lo) ----
    auto load_stage = [&](int s) {
        const int k0 = s * 32;
        const uint32_t stb = sbase + (s & 1) * STG;
        #pragma unroll
        for (int i = 0; i < 2; i++) {
            int cid = i * 256 + tid;          // 0..511
            int row = cid >> 2, c = cid & 3;
            uint32_t so = stb + row * RSTR + c * 16;
            size_t go = ((size_t)(arow0 + row) * KTOT + k0 + c * 8) * 2;
            cp16(so, pAh + go);
            cp16(so + PL_SZ, pAl + go);
        }
        #pragma unroll
        for (int i = 0; i < 2; i++) {
            int cid = i * 256 + tid;
            int row = cid >> 2, c = cid & 3;
            uint32_t so = stb + OFF_B + row * RSTR + c * 16;
            size_t go = ((size_t)(brow0 + row) * KTOT + k0 + c * 8) * 2;
            cp16(so, pBh + go);
            cp16(so + PL_SZ, pBl + go);
        }
        CP_COMMIT();
    };

    // ldmatrix lane addressing: lane -> (row-in-16, half)
    const int lrow = (lane & 7) | (((lane >> 3) & 1) << 3);   // 0..15
    const int lhalf = lane >> 4;                              // k chunk 0/1

    float acc[4][4][4];
    #pragma unroll
    for (int i = 0; i < 4; i++)
        #pragma unroll
        for (int j = 0; j < 4; j++)
            #pragma unroll
            for (int q = 0; q < 4; q++) acc[i][j][q] = 0.f;

    load_stage(0);

    for (int s = 0; s < NS; s++) {
        if (s + 1 < NS) { load_stage(s + 1); CP_WAIT(1); }
        else            { CP_WAIT(0); }
        __syncthreads();

        const uint32_t stb = sbase + (s & 1) * STG;
        const uint32_t aA = stb + (wm * 64 + lrow) * RSTR + lhalf * 16;
        const uint32_t aB = stb + OFF_B + (wn * 32 + lrow) * RSTR + lhalf * 16;

        #pragma unroll
        for (int kk = 0; kk < 32; kk += 16) {
            const uint32_t kb = kk * 2;
            uint32_t ah[4][4], al[4][4], bh[4][2], bl[4][2];
            #pragma unroll
            for (int i = 0; i < 4; i++) ldm4(ah[i], aA + i * 16 * RSTR + kb);
            #pragma unroll
            for (int i = 0; i < 4; i++) ldm4(al[i], aA + PL_SZ + i * 16 * RSTR + kb);
            #pragma unroll
            for (int jj = 0; jj < 2; jj++) {
                uint32_t t[4];
                ldm4(t, aB + jj * 16 * RSTR + kb);
                bh[jj*2][0] = t[0]; bh[jj*2+1][0] = t[1];
                bh[jj*2][1] = t[2]; bh[jj*2+1][1] = t[3];
                ldm4(t, aB + PL_SZ + jj * 16 * RSTR + kb);
                bl[jj*2][0] = t[0]; bl[jj*2+1][0] = t[1];
                bl[jj*2][1] = t[2]; bl[jj*2+1][1] = t[3];
            }
            #pragma unroll
            for (int i = 0; i < 4; i++)
                #pragma unroll
                for (int j = 0; j < 4; j++) {
                    mma16816(acc[i][j], ah[i], bh[j]);
                    mma16816(acc[i][j], al[i], bh[j]);
                    mma16816(acc[i][j], ah[i], bl[j]);
                }
        }
        __syncthreads();
    }

    // ---- epilogue ----
    const float* bias_v = bias + (size_t)view * NTOT;
    const int g4 = lane >> 2, t4 = lane & 3;

    #pragma unroll
    for (int i = 0; i < 4; i++) {
        #pragma unroll
        for (int j = 0; j < 4; j++) {
            const int row0 = grow + wm * 64 + i * 16 + g4;
            const int col  = gcol + wn * 32 + j * 8 + t4 * 2;
            const float b0 = __ldg(bias_v + col);
            const float b1 = __ldg(bias_v + col + 1);
            #pragma unroll
            for (int h = 0; h < 2; h++) {
                const int rw = row0 + h * 8;
                float v0 = acc[i][j][h * 2 + 0] + b0;
                float v1 = acc[i][j][h * 2 + 1] + b1;
                const size_t go = (size_t)rw * NTOT + col;
                if (GELU) {
                    v0 = 0.5f * v0 * (1.0f + erff(v0 * 0.70710678118654752f));
                    v1 = 0.5f * v1 * (1.0f + erff(v1 * 0.70710678118654752f));
                    __nv_bfloat16 h0 = __float2bfloat16(v0);
                    __nv_bfloat16 h1 = __float2bfloat16(v1);
                    __nv_bfloat16 l0 = __float2bfloat16(v0 - __bfloat162float(h0));
                    __nv_bfloat16 l1 = __float2bfloat16(v1 - __bfloat162float(h1));
                    *(__nv_bfloat162*)(outH + go) = __nv_bfloat162(h0, h1);
                    *(__nv_bfloat162*)(outL + go) = __nv_bfloat162(l0, l1);
                } else {
                    float2 xv = *(const float2*)(xres + go);
                    float2 o;
                    o.x = xv.x + v0;
                    o.y = xv.y + v1;
                    *(float2*)(outp + go) = o;
                }
            }
        }
    }
}

// ---------------------------------------------------------------------------
// Launch
// ---------------------------------------------------------------------------
extern "C" void kernel_launch(void* const* d_in, const int* in_sizes, int n_in,
                              void* d_out, int out_size) {
    const float* x     = (const float*)d_in[0];
    const int*   idx   = (const int*)  d_in[1];
    const float* gamma = (const float*)d_in[2];
    const float* beta  = (const float*)d_in[3];
    const float* W1    = (const float*)d_in[4];
    const float* b1    = (const float*)d_in[5];
    const float* W2    = (const float*)d_in[6];
    const float* b2    = (const float*)d_in[7];
    float* out = (float*)d_out;

    void *p_xah, *p_xal, *p_hh, *p_hl, *p_w1h, *p_w1l, *p_w2h, *p_w2l;
    cudaGetSymbolAddress(&p_xah, g_xah);
    cudaGetSymbolAddress(&p_xal, g_xal);
    cudaGetSymbolAddress(&p_hh,  g_hh);
    cudaGetSymbolAddress(&p_hl,  g_hl);
    cudaGetSymbolAddress(&p_w1h, g_w1h);
    cudaGetSymbolAddress(&p_w1l, g_w1l);
    cudaGetSymbolAddress(&p_w2h, g_w2h);
    cudaGetSymbolAddress(&p_w2l, g_w2l);

    cudaFuncSetAttribute(gemm_mma<DIM, HID, true>,
                         cudaFuncAttributeMaxDynamicSharedMemorySize, SMEM_DYN);
    cudaFuncSetAttribute(gemm_mma<HID, DIM, false>,
                         cudaFuncAttributeMaxDynamicSharedMemorySize, SMEM_DYN);

    decode_idx_kernel<<<1, 1>>>(idx);
    ln_kernel<<<ROWS, 256>>>(x, gamma, beta);
    wt_kernel<<<dim3(HID / 32, DIM / 32, NVIEW), dim3(32, 8)>>>(
        W1, (__nv_bfloat16*)p_w1h, (__nv_bfloat16*)p_w1l, DIM, HID);
    wt_kernel<<<dim3(DIM / 32, HID / 32, NVIEW), dim3(32, 8)>>>(
        W2, (__nv_bfloat16*)p_w2h, (__nv_bfloat16*)p_w2l, HID, DIM);

    // GEMM1: h = GELU(xn @ W1 + b1)   [8192x2048]x[2048x8192]
    gemm_mma<DIM, HID, true><<<(ROWS / 128) * (HID / 128), 256, SMEM_DYN>>>(
        (const __nv_bfloat16*)p_xah, (const __nv_bfloat16*)p_xal,
        (const __nv_bfloat16*)p_w1h, (const __nv_bfloat16*)p_w1l,
        b1, nullptr, nullptr,
        (__nv_bfloat16*)p_hh, (__nv_bfloat16*)p_hl);

    // GEMM2: out = x + h @ W2 + b2    [8192x8192]x[8192x2048]
    gemm_mma<HID, DIM, false><<<(ROWS / 128) * (DIM / 128), 256, SMEM_DYN>>>(
        (const __nv_bfloat16*)p_hh, (const __nv_bfloat16*)p_hl,
        (const __nv_bfloat16*)p_w2h, (const __nv_bfloat16*)p_w2l,
        b2, x, out, nullptr, nullptr);
}

// round 7
// speedup vs baseline: 1.8784x; 1.0670x over previous
#include <cuda_runtime.h>
#include <cuda_bf16.h>
#include <math.h>
#include <stdint.h>

// Problem dims
#define BATCH 32
#define PTOK  256
#define DIM   2048
#define HID   8192
#define NVIEW 3
#define ROWS  (BATCH * PTOK)   // 8192

// ---------------------------------------------------------------------------
// Device scratch (static; no cudaMalloc allowed)
// ---------------------------------------------------------------------------
__device__ int g_idx[BATCH];
__device__ int g_morder[ROWS / 128];   // M-tiles sorted by view

__device__ __nv_bfloat16 g_xah[(size_t)ROWS * DIM];
__device__ __nv_bfloat16 g_xal[(size_t)ROWS * DIM];
__device__ __nv_bfloat16 g_hh [(size_t)ROWS * HID];
__device__ __nv_bfloat16 g_hl [(size_t)ROWS * HID];
__device__ __nv_bfloat16 g_w1h[(size_t)NVIEW * HID * DIM];  // [v][n=HID][k=DIM]
__device__ __nv_bfloat16 g_w1l[(size_t)NVIEW * HID * DIM];
__device__ __nv_bfloat16 g_w2h[(size_t)NVIEW * DIM * HID];  // [v][n=DIM][k=HID]
__device__ __nv_bfloat16 g_w2l[(size_t)NVIEW * DIM * HID];

// ---------------------------------------------------------------------------
// PTX helpers (base sm_103-safe: mma.sync / ldmatrix / cp.async only)
// ---------------------------------------------------------------------------
__device__ __forceinline__ uint32_t smem_u32(const void* p) {
    uint32_t a;
    asm("{ .reg .u64 t; cvta.to.shared.u64 t, %1; cvt.u32.u64 %0, t; }"
        : "=r"(a) : "l"(p));
    return a;
}

__device__ __forceinline__ void cp16(uint32_t dst, const void* src) {
    asm volatile("cp.async.cg.shared.global [%0], [%1], 16;" :: "r"(dst), "l"(src));
}
#define CP_COMMIT() asm volatile("cp.async.commit_group;" ::: "memory")
#define CP_WAIT(n)  asm volatile("cp.async.wait_group %0;" :: "n"(n) : "memory")

__device__ __forceinline__ void ldm4(uint32_t* r, uint32_t a) {
    asm volatile("ldmatrix.sync.aligned.m8n8.x4.shared.b16 {%0,%1,%2,%3}, [%4];"
        : "=r"(r[0]), "=r"(r[1]), "=r"(r[2]), "=r"(r[3]) : "r"(a));
}

__device__ __forceinline__ void mma16816(float* c, const uint32_t* a, const uint32_t* b) {
    asm volatile(
        "mma.sync.aligned.m16n8k16.row.col.f32.bf16.bf16.f32 "
        "{%0,%1,%2,%3}, {%4,%5,%6,%7}, {%8,%9}, {%0,%1,%2,%3};"
        : "+f"(c[0]), "+f"(c[1]), "+f"(c[2]), "+f"(c[3])
        : "r"(a[0]), "r"(a[1]), "r"(a[2]), "r"(a[3]), "r"(b[0]), "r"(b[1]));
}

// ---------------------------------------------------------------------------
// decode idx + build view-sorted M-tile order
// ---------------------------------------------------------------------------
__global__ void decode_idx_kernel(const int* __restrict__ p) {
    bool is64 = true;
    for (int b = 0; b < BATCH; b++) {
        int lo = p[2 * b], hi = p[2 * b + 1];
        if (!(lo >= 0 && lo < NVIEW && hi == 0)) { is64 = false; break; }
    }
    for (int b = 0; b < BATCH; b++) g_idx[b] = is64 ? p[2 * b] : p[b];
    int c = 0;
    for (int v = 0; v < NVIEW; v++)
        for (int s = 0; s < BATCH; s++)
            if (g_idx[s] == v) { g_morder[c++] = 2 * s; g_morder[c++] = 2 * s + 1; }
}

// ---------------------------------------------------------------------------
// LayerNorm -> bf16 hi/lo planes
// ---------------------------------------------------------------------------
__global__ void __launch_bounds__(256) ln_kernel(
    const float* __restrict__ x,
    const float* __restrict__ gamma,
    const float* __restrict__ beta)
{
    const int row = blockIdx.x;
    const int view = g_idx[row >> 8];
    const float* xr = x + (size_t)row * DIM;
    const int tid = threadIdx.x;

    float4 v0 = *(const float4*)(xr + tid * 4);
    float4 v1 = *(const float4*)(xr + 1024 + tid * 4);

    float s  = v0.x + v0.y + v0.z + v0.w + v1.x + v1.y + v1.z + v1.w;
    float ss = v0.x*v0.x + v0.y*v0.y + v0.z*v0.z + v0.w*v0.w
             + v1.x*v1.x + v1.y*v1.y + v1.z*v1.z + v1.w*v1.w;
    #pragma unroll
    for (int off = 16; off > 0; off >>= 1) {
        s  += __shfl_xor_sync(0xffffffffu, s,  off);
        ss += __shfl_xor_sync(0xffffffffu, ss, off);
    }
    __shared__ float rs[8], rss[8];
    int wid = tid >> 5, lane = tid & 31;
    if (lane == 0) { rs[wid] = s; rss[wid] = ss; }
    __syncthreads();
    if (wid == 0) {
        float a = (lane < 8) ? rs[lane] : 0.f;
        float b = (lane < 8) ? rss[lane] : 0.f;
        #pragma unroll
        for (int off = 4; off > 0; off >>= 1) {
            a += __shfl_xor_sync(0xffffffffu, a, off);
            b += __shfl_xor_sync(0xffffffffu, b, off);
        }
        if (lane == 0) { rs[0] = a; rss[0] = b; }
    }
    __syncthreads();
    const float mean = rs[0] * (1.0f / DIM);
    const float var  = rss[0] * (1.0f / DIM) - mean * mean;
    const float inv  = rsqrtf(var + 1e-5f);

    const float* g = gamma + (size_t)view * DIM;
    const float* b = beta  + (size_t)view * DIM;
    size_t base = (size_t)row * DIM;

    float v[8];
    v[0]=v0.x; v[1]=v0.y; v[2]=v0.z; v[3]=v0.w; v[4]=v1.x; v[5]=v1.y; v[6]=v1.z; v[7]=v1.w;
    #pragma unroll
    for (int j = 0; j < 8; j++) {
        int c = (j < 4) ? (tid * 4 + j) : (1024 + tid * 4 + (j - 4));
        float o = (v[j] - mean) * inv * g[c] + b[c];
        __nv_bfloat16 hi = __float2bfloat16(o);
        __nv_bfloat16 lo = __float2bfloat16(o - __bfloat162float(hi));
        g_xah[base + c] = hi;
        g_xal[base + c] = lo;
    }
}

// ---------------------------------------------------------------------------
// Weight transpose + bf16 split: W [v][K][N] fp32 -> out [v][N][K] hi/lo bf16
// ---------------------------------------------------------------------------
__global__ void __launch_bounds__(256) wt_kernel(
    const float* __restrict__ W,
    __nv_bfloat16* __restrict__ oh,
    __nv_bfloat16* __restrict__ ol,
    int K, int N)
{
    __shared__ float t[32][33];
    int n0 = blockIdx.x * 32, k0 = blockIdx.y * 32, v = blockIdx.z;
    int tx = threadIdx.x, ty = threadIdx.y;
    const float* src = W + ((size_t)v * K + k0) * N + n0;
    #pragma unroll
    for (int i = 0; i < 4; i++)
        t[ty + 8 * i][tx] = src[(size_t)(ty + 8 * i) * N + tx];
    __syncthreads();
    #pragma unroll
    for (int i = 0; i < 4; i++) {
        float val = t[tx][ty + 8 * i];
        __nv_bfloat16 hi = __float2bfloat16(val);
        __nv_bfloat16 lo = __float2bfloat16(val - __bfloat162float(hi));
        size_t o = ((size_t)v * N + n0 + ty + 8 * i) * K + k0 + tx;
        oh[o] = hi;
        ol[o] = lo;
    }
}

// ---------------------------------------------------------------------------
// Warp-MMA GEMM: D[128x256] = A[128xK] @ B[256xK]^T  (bf16 hi/lo split)
// 512 threads = 16 warps in 4(M) x 4(N); warp tile 32x64.
// 3-stage cp.async ring; 80B smem row stride (conflict-free ldmatrix).
// ---------------------------------------------------------------------------
#define RSTR   80                       // smem row stride (bytes), 32 bf16 used
#define A_PL   (128 * RSTR)             // 10240 per A plane
#define B_PL   (256 * RSTR)             // 20480 per B plane
#define OFF_B  (2 * A_PL)               // B planes after A hi/lo
#define STG    (2 * A_PL + 2 * B_PL)    // 61440 per stage
#define NSTAGE 3
#define SMEM_DYN (NSTAGE * STG)         // 184320

template<int KTOT, int NTOT, bool GELU>
__global__ void __launch_bounds__(512, 1) gemm_mma(
    const __nv_bfloat16* __restrict__ Ah, const __nv_bfloat16* __restrict__ Al,
    const __nv_bfloat16* __restrict__ Bh, const __nv_bfloat16* __restrict__ Bl,
    const float* __restrict__ bias,
    const float* __restrict__ xres, float* __restrict__ outp,
    __nv_bfloat16* __restrict__ outH, __nv_bfloat16* __restrict__ outL)
{
    constexpr int NS = KTOT / 32;
    extern __shared__ char smem[];
    const uint32_t sbase = smem_u32(smem);
    const int tid = threadIdx.x;
    const int lane = tid & 31;
    const int wrp = tid >> 5;
    const int wm = wrp & 3;          // 0..3 (M, 32 rows each)
    const int wn = wrp >> 2;         // 0..3 (N, 64 cols each)

    // block mapping: groups of 4 N-tiles x all 64 view-sorted M-tiles
    const int bx = blockIdx.x;
    const int g = bx >> 8, r = bx & 255;
    const int mb = g_morder[r >> 2];
    const int nb = (g << 2) | (r & 3);
    const int view = g_idx[mb >> 1];
    const int grow = mb * 128;
    const size_t arow0 = (size_t)grow;
    const size_t brow0 = (size_t)view * NTOT + (size_t)nb * 256;
    const int gcol = nb * 256;

    const char* pAh = (const char*)Ah;
    const char* pAl = (const char*)Al;
    const char* pBh = (const char*)Bh;
    const char* pBl = (const char*)Bl;

    // ---- stage loader: A 128 rows x 32 k, B 256 rows x 32 k, hi+lo ----
    auto load_stage = [&](int s) {
        const int k0 = s * 32;
        const uint32_t stb = sbase + (s % NSTAGE) * STG;
        {
            int row = tid >> 2, c = tid & 3;               // 512 = 128 rows x 4 segs
            uint32_t so = stb + row * RSTR + c * 16;
            size_t go = ((size_t)(arow0 + row) * KTOT + k0 + c * 8) * 2;
            cp16(so, pAh + go);
            cp16(so + A_PL, pAl + go);
        }
        #pragma unroll
        for (int i = 0; i < 2; i++) {
            int cid = i * 512 + tid;                       // 1024 = 256 rows x 4 segs
            int row = cid >> 2, c = cid & 3;
            uint32_t so = stb + OFF_B + row * RSTR + c * 16;
            size_t go = ((size_t)(brow0 + row) * KTOT + k0 + c * 8) * 2;
            cp16(so, pBh + go);
            cp16(so + B_PL, pBl + go);
        }
        CP_COMMIT();
    };

    // ldmatrix lane addressing
    const int lrow = (lane & 7) | (((lane >> 3) & 1) << 3);   // 0..15
    const int lhalf = lane >> 4;                              // 0/1

    float acc[2][8][4];
    #pragma unroll
    for (int i = 0; i < 2; i++)
        #pragma unroll
        for (int j = 0; j < 8; j++)
            #pragma unroll
            for (int q = 0; q < 4; q++) acc[i][j][q] = 0.f;

    load_stage(0);
    load_stage(1);

    for (int s = 0; s < NS; s++) {
        if (s == NS - 1) { CP_WAIT(0); }
        else             { CP_WAIT(1); }
        __syncthreads();
        if (s + 2 < NS) load_stage(s + 2);

        const uint32_t stb = sbase + (s % NSTAGE) * STG;
        const uint32_t aA = stb + (wm * 32 + lrow) * RSTR + lhalf * 16;
        const uint32_t aB = stb + OFF_B + (wn * 64 + lrow) * RSTR + lhalf * 16;

        #pragma unroll
        for (int kk = 0; kk < 32; kk += 16) {
            const uint32_t kb = kk * 2;
            uint32_t ah[2][4], al[2][4];
            ldm4(ah[0], aA + kb);
            ldm4(ah[1], aA + 16 * RSTR + kb);
            ldm4(al[0], aA + A_PL + kb);
            ldm4(al[1], aA + A_PL + 16 * RSTR + kb);
            #pragma unroll
            for (int j16 = 0; j16 < 4; j16++) {
                uint32_t th[4], tl[4];
                ldm4(th, aB + j16 * 16 * RSTR + kb);
                ldm4(tl, aB + B_PL + j16 * 16 * RSTR + kb);
                uint32_t bh0[2] = { th[0], th[2] };
                uint32_t bh1[2] = { th[1], th[3] };
                uint32_t bl0[2] = { tl[0], tl[2] };
                uint32_t bl1[2] = { tl[1], tl[3] };
                #pragma unroll
                for (int i = 0; i < 2; i++) {
                    mma16816(acc[i][2*j16],   ah[i], bh0);
                    mma16816(acc[i][2*j16],   al[i], bh0);
                    mma16816(acc[i][2*j16],   ah[i], bl0);
                    mma16816(acc[i][2*j16+1], ah[i], bh1);
                    mma16816(acc[i][2*j16+1], al[i], bh1);
                    mma16816(acc[i][2*j16+1], ah[i], bl1);
                }
            }
        }
    }

    // ---- epilogue ----
    const float* bias_v = bias + (size_t)view * NTOT;
    const int g4 = lane >> 2, t4 = lane & 3;

    #pragma unroll
    for (int i = 0; i < 2; i++) {
        #pragma unroll
        for (int j = 0; j < 8; j++) {
            const int row0 = grow + wm * 32 + i * 16 + g4;
            const int col  = gcol + wn * 64 + j * 8 + t4 * 2;
            const float b0 = __ldg(bias_v + col);
            const float b1 = __ldg(bias_v + col + 1);
            #pragma unroll
            for (int h = 0; h < 2; h++) {
                const int rw = row0 + h * 8;
                float v0 = acc[i][j][h * 2 + 0] + b0;
                float v1 = acc[i][j][h * 2 + 1] + b1;
                const size_t go = (size_t)rw * NTOT + col;
                if (GELU) {
                    v0 = 0.5f * v0 * (1.0f + erff(v0 * 0.70710678118654752f));
                    v1 = 0.5f * v1 * (1.0f + erff(v1 * 0.70710678118654752f));
                    __nv_bfloat16 h0 = __float2bfloat16(v0);
                    __nv_bfloat16 h1 = __float2bfloat16(v1);
                    __nv_bfloat16 l0 = __float2bfloat16(v0 - __bfloat162float(h0));
                    __nv_bfloat16 l1 = __float2bfloat16(v1 - __bfloat162float(h1));
                    *(__nv_bfloat162*)(outH + go) = __nv_bfloat162(h0, h1);
                    *(__nv_bfloat162*)(outL + go) = __nv_bfloat162(l0, l1);
                } else {
                    float2 xv = *(const float2*)(xres + go);
                    float2 o;
                    o.x = xv.x + v0;
                    o.y = xv.y + v1;
                    *(float2*)(outp + go) = o;
                }
            }
        }
    }
}

// ---------------------------------------------------------------------------
// Launch
// ---------------------------------------------------------------------------
extern "C" void kernel_launch(void* const* d_in, const int* in_sizes, int n_in,
                              void* d_out, int out_size) {
    const float* x     = (const float*)d_in[0];
    const int*   idx   = (const int*)  d_in[1];
    const float* gamma = (const float*)d_in[2];
    const float* beta  = (const float*)d_in[3];
    const float* W1    = (const float*)d_in[4];
    const float* b1    = (const float*)d_in[5];
    const float* W2    = (const float*)d_in[6];
    const float* b2    = (const float*)d_in[7];
    float* out = (float*)d_out;

    void *p_xah, *p_xal, *p_hh, *p_hl, *p_w1h, *p_w1l, *p_w2h, *p_w2l;
    cudaGetSymbolAddress(&p_xah, g_xah);
    cudaGetSymbolAddress(&p_xal, g_xal);
    cudaGetSymbolAddress(&p_hh,  g_hh);
    cudaGetSymbolAddress(&p_hl,  g_hl);
    cudaGetSymbolAddress(&p_w1h, g_w1h);
    cudaGetSymbolAddress(&p_w1l, g_w1l);
    cudaGetSymbolAddress(&p_w2h, g_w2h);
    cudaGetSymbolAddress(&p_w2l, g_w2l);

    cudaFuncSetAttribute(gemm_mma<DIM, HID, true>,
                         cudaFuncAttributeMaxDynamicSharedMemorySize, SMEM_DYN);
    cudaFuncSetAttribute(gemm_mma<HID, DIM, false>,
                         cudaFuncAttributeMaxDynamicSharedMemorySize, SMEM_DYN);

    decode_idx_kernel<<<1, 1>>>(idx);
    ln_kernel<<<ROWS, 256>>>(x, gamma, beta);
    wt_kernel<<<dim3(HID / 32, DIM / 32, NVIEW), dim3(32, 8)>>>(
        W1, (__nv_bfloat16*)p_w1h, (__nv_bfloat16*)p_w1l, DIM, HID);
    wt_kernel<<<dim3(DIM / 32, HID / 32, NVIEW), dim3(32, 8)>>>(
        W2, (__nv_bfloat16*)p_w2h, (__nv_bfloat16*)p_w2l, HID, DIM);

    // GEMM1: h = GELU(xn @ W1 + b1)   [8192x2048]x[2048x8192]
    gemm_mma<DIM, HID, true><<<(ROWS / 128) * (HID / 256), 512, SMEM_DYN>>>(
        (const __nv_bfloat16*)p_xah, (const __nv_bfloat16*)p_xal,
        (const __nv_bfloat16*)p_w1h, (const __nv_bfloat16*)p_w1l,
        b1, nullptr, nullptr,
        (__nv_bfloat16*)p_hh, (__nv_bfloat16*)p_hl);

    // GEMM2: out = x + h @ W2 + b2    [8192x8192]x[8192x2048]
    gemm_mma<HID, DIM, false><<<(ROWS / 128) * (DIM / 256), 512, SMEM_DYN>>>(
        (const __nv_bfloat16*)p_hh, (const __nv_bfloat16*)p_hl,
        (const __nv_bfloat16*)p_w2h, (const __nv_bfloat16*)p_w2l,
        b2, x, out, nullptr, nullptr);
}

// round 8
// speedup vs baseline: 2.1058x; 1.1210x over previous
#include <cuda_runtime.h>
#include <cuda_fp16.h>
#include <math.h>
#include <stdint.h>

// Problem dims
#define BATCH 32
#define PTOK  256
#define DIM   2048
#define HID   8192
#define NVIEW 3
#define ROWS  (BATCH * PTOK)   // 8192

// ---------------------------------------------------------------------------
// Device scratch
// ---------------------------------------------------------------------------
__device__ int g_idx[BATCH];
__device__ int g_morder[ROWS / 128];

__device__ __half g_xah[(size_t)ROWS * DIM];
__device__ __half g_xal[(size_t)ROWS * DIM];
__device__ __half g_hh [(size_t)ROWS * HID];
__device__ __half g_hl [(size_t)ROWS * HID];
__device__ __half g_w1h[(size_t)NVIEW * HID * DIM];  // [v][n][k]
__device__ __half g_w1l[(size_t)NVIEW * HID * DIM];
__device__ __half g_w2h[(size_t)NVIEW * DIM * HID];
__device__ __half g_w2l[(size_t)NVIEW * DIM * HID];

// ---------------------------------------------------------------------------
// PTX helpers (base sm_103-safe)
// ---------------------------------------------------------------------------
__device__ __forceinline__ uint32_t smem_u32(const void* p) {
    uint32_t a;
    asm("{ .reg .u64 t; cvta.to.shared.u64 t, %1; cvt.u32.u64 %0, t; }"
        : "=r"(a) : "l"(p));
    return a;
}

__device__ __forceinline__ void cp16(uint32_t dst, const void* src) {
    asm volatile("cp.async.cg.shared.global [%0], [%1], 16;" :: "r"(dst), "l"(src));
}
#define CP_COMMIT() asm volatile("cp.async.commit_group;" ::: "memory")
#define CP_WAIT(n)  asm volatile("cp.async.wait_group %0;" :: "n"(n) : "memory")

__device__ __forceinline__ void ldm4(uint32_t* r, uint32_t a) {
    asm volatile("ldmatrix.sync.aligned.m8n8.x4.shared.b16 {%0,%1,%2,%3}, [%4];"
        : "=r"(r[0]), "=r"(r[1]), "=r"(r[2]), "=r"(r[3]) : "r"(a));
}

// fp16 inputs, fp32 accumulator (main term)
__device__ __forceinline__ void mma_f32(float* c, const uint32_t* a, const uint32_t* b) {
    asm volatile(
        "mma.sync.aligned.m16n8k16.row.col.f32.f16.f16.f32 "
        "{%0,%1,%2,%3}, {%4,%5,%6,%7}, {%8,%9}, {%0,%1,%2,%3};"
        : "+f"(c[0]), "+f"(c[1]), "+f"(c[2]), "+f"(c[3])
        : "r"(a[0]), "r"(a[1]), "r"(a[2]), "r"(a[3]), "r"(b[0]), "r"(b[1]));
}

// fp16 inputs, fp16 accumulator (cross terms — small magnitude)
__device__ __forceinline__ void mma_f16(uint32_t* c, const uint32_t* a, const uint32_t* b) {
    asm volatile(
        "mma.sync.aligned.m16n8k16.row.col.f16.f16.f16.f16 "
        "{%0,%1}, {%2,%3,%4,%5}, {%6,%7}, {%0,%1};"
        : "+r"(c[0]), "+r"(c[1])
        : "r"(a[0]), "r"(a[1]), "r"(a[2]), "r"(a[3]), "r"(b[0]), "r"(b[1]));
}

// ---------------------------------------------------------------------------
// decode idx + view-sorted M-tile order
// ---------------------------------------------------------------------------
__global__ void decode_idx_kernel(const int* __restrict__ p) {
    bool is64 = true;
    for (int b = 0; b < BATCH; b++) {
        int lo = p[2 * b], hi = p[2 * b + 1];
        if (!(lo >= 0 && lo < NVIEW && hi == 0)) { is64 = false; break; }
    }
    for (int b = 0; b < BATCH; b++) g_idx[b] = is64 ? p[2 * b] : p[b];
    int c = 0;
    for (int v = 0; v < NVIEW; v++)
        for (int s = 0; s < BATCH; s++)
            if (g_idx[s] == v) { g_morder[c++] = 2 * s; g_morder[c++] = 2 * s + 1; }
}

// ---------------------------------------------------------------------------
// LayerNorm -> fp16 hi/lo planes
// ---------------------------------------------------------------------------
__global__ void __launch_bounds__(256) ln_kernel(
    const float* __restrict__ x,
    const float* __restrict__ gamma,
    const float* __restrict__ beta)
{
    const int row = blockIdx.x;
    const int view = g_idx[row >> 8];
    const float* xr = x + (size_t)row * DIM;
    const int tid = threadIdx.x;

    float4 v0 = *(const float4*)(xr + tid * 4);
    float4 v1 = *(const float4*)(xr + 1024 + tid * 4);

    float s  = v0.x + v0.y + v0.z + v0.w + v1.x + v1.y + v1.z + v1.w;
    float ss = v0.x*v0.x + v0.y*v0.y + v0.z*v0.z + v0.w*v0.w
             + v1.x*v1.x + v1.y*v1.y + v1.z*v1.z + v1.w*v1.w;
    #pragma unroll
    for (int off = 16; off > 0; off >>= 1) {
        s  += __shfl_xor_sync(0xffffffffu, s,  off);
        ss += __shfl_xor_sync(0xffffffffu, ss, off);
    }
    __shared__ float rs[8], rss[8];
    int wid = tid >> 5, lane = tid & 31;
    if (lane == 0) { rs[wid] = s; rss[wid] = ss; }
    __syncthreads();
    if (wid == 0) {
        float a = (lane < 8) ? rs[lane] : 0.f;
        float b = (lane < 8) ? rss[lane] : 0.f;
        #pragma unroll
        for (int off = 4; off > 0; off >>= 1) {
            a += __shfl_xor_sync(0xffffffffu, a, off);
            b += __shfl_xor_sync(0xffffffffu, b, off);
        }
        if (lane == 0) { rs[0] = a; rss[0] = b; }
    }
    __syncthreads();
    const float mean = rs[0] * (1.0f / DIM);
    const float var  = rss[0] * (1.0f / DIM) - mean * mean;
    const float inv  = rsqrtf(var + 1e-5f);

    const float* g = gamma + (size_t)view * DIM;
    const float* b = beta  + (size_t)view * DIM;
    size_t base = (size_t)row * DIM;

    float v[8];
    v[0]=v0.x; v[1]=v0.y; v[2]=v0.z; v[3]=v0.w; v[4]=v1.x; v[5]=v1.y; v[6]=v1.z; v[7]=v1.w;
    #pragma unroll
    for (int j = 0; j < 8; j++) {
        int c = (j < 4) ? (tid * 4 + j) : (1024 + tid * 4 + (j - 4));
        float o = (v[j] - mean) * inv * g[c] + b[c];
        __half hi = __float2half_rn(o);
        __half lo = __float2half_rn(o - __half2float(hi));
        g_xah[base + c] = hi;
        g_xal[base + c] = lo;
    }
}

// ---------------------------------------------------------------------------
// Fused weight transpose + fp16 split for BOTH W1 and W2 (one launch)
// blockIdx.y in [0,6): y<3 -> W1 view y ; y>=3 -> W2 view y-3
// ---------------------------------------------------------------------------
__global__ void __launch_bounds__(256) wt_all_kernel(
    const float* __restrict__ W1, const float* __restrict__ W2)
{
    __shared__ float t[32][33];
    const int yy = blockIdx.y;
    const bool isW1 = (yy < 3);
    const int v = isW1 ? yy : (yy - 3);
    const int K = isW1 ? DIM : HID;
    const int N = isW1 ? HID : DIM;
    const float* W = isW1 ? W1 : W2;
    __half* oh = isW1 ? g_w1h : g_w2h;
    __half* ol = isW1 ? g_w1l : g_w2l;

    const int nblk = N / 32;
    const int kb = blockIdx.x / nblk;
    const int nb = blockIdx.x % nblk;
    const int n0 = nb * 32, k0 = kb * 32;
    const int tx = threadIdx.x, ty = threadIdx.y;

    const float* src = W + ((size_t)v * K + k0) * N + n0;
    #pragma unroll
    for (int i = 0; i < 4; i++)
        t[ty + 8 * i][tx] = src[(size_t)(ty + 8 * i) * N + tx];
    __syncthreads();
    #pragma unroll
    for (int i = 0; i < 4; i++) {
        float val = t[tx][ty + 8 * i];
        __half hi = __float2half_rn(val);
        __half lo = __float2half_rn(val - __half2float(hi));
        size_t o = ((size_t)v * N + n0 + ty + 8 * i) * K + k0 + tx;
        oh[o] = hi;
        ol[o] = lo;
    }
}

// ---------------------------------------------------------------------------
// Warp-MMA GEMM: D[128x256] = A[128xK] @ B[256xK]^T  (fp16 hi/lo, 3 terms)
// main term -> fp32 acc ; both cross terms -> shared fp16 acc.
// 512 threads = 16 warps (4M x 4N), warp tile 32x64.
// K-chunk 64, 2-stage cp.async double buffer. RSTR=144 (conflict-free ldmatrix).
// ---------------------------------------------------------------------------
#define KC     64
#define RSTR   144
#define A_PL   (128 * RSTR)             // 18432
#define B_PL   (256 * RSTR)             // 36864
#define STG    (2 * A_PL + 2 * B_PL)    // 110592
#define SMEM_DYN (2 * STG)              // 221184

template<int KTOT, int NTOT, bool GELU>
__global__ void __launch_bounds__(512, 1) gemm_mma(
    const __half* __restrict__ Ah, const __half* __restrict__ Al,
    const __half* __restrict__ Bh, const __half* __restrict__ Bl,
    const float* __restrict__ bias,
    const float* __restrict__ xres, float* __restrict__ outp,
    __half* __restrict__ outH, __half* __restrict__ outL)
{
    constexpr int NS = KTOT / KC;
    extern __shared__ char smem[];
    const uint32_t sbase = smem_u32(smem);
    const int tid = threadIdx.x;
    const int lane = tid & 31;
    const int wrp = tid >> 5;
    const int wm = wrp & 3;          // M warp (32 rows)
    const int wn = wrp >> 2;         // N warp (64 cols)

    const int bx = blockIdx.x;
    const int g = bx >> 8, r = bx & 255;
    const int mb = g_morder[r >> 2];
    const int nb = (g << 2) | (r & 3);
    const int view = g_idx[mb >> 1];
    const int grow = mb * 128;
    const size_t arow0 = (size_t)grow;
    const size_t brow0 = (size_t)view * NTOT + (size_t)nb * 256;
    const int gcol = nb * 256;

    const char* pAh = (const char*)Ah;
    const char* pAl = (const char*)Al;
    const char* pBh = (const char*)Bh;
    const char* pBl = (const char*)Bl;

    auto load_stage = [&](int s) {
        const int k0 = s * KC;
        const uint32_t stb = sbase + (s & 1) * STG;
        #pragma unroll
        for (int i = 0; i < 2; i++) {
            int cid = i * 512 + tid;              // 1024 = 128 rows x 8 chunks
            int row = cid >> 3, c = cid & 7;
            uint32_t so = stb + row * RSTR + c * 16;
            size_t go = ((size_t)(arow0 + row) * KTOT + k0 + c * 8) * 2;
            cp16(so, pAh + go);
            cp16(so + A_PL, pAl + go);
        }
        #pragma unroll
        for (int i = 0; i < 4; i++) {
            int cid = i * 512 + tid;              // 2048 = 256 rows x 8 chunks
            int row = cid >> 3, c = cid & 7;
            uint32_t so = stb + 2 * A_PL + row * RSTR + c * 16;
            size_t go = ((size_t)(brow0 + row) * KTOT + k0 + c * 8) * 2;
            cp16(so, pBh + go);
            cp16(so + B_PL, pBl + go);
        }
        CP_COMMIT();
    };

    const int lrow = (lane & 7) | (((lane >> 3) & 1) << 3);
    const int lhalf = lane >> 4;

    float    acc [2][8][4];
    uint32_t accX[2][8][2];
    #pragma unroll
    for (int i = 0; i < 2; i++)
        #pragma unroll
        for (int j = 0; j < 8; j++) {
            #pragma unroll
            for (int q = 0; q < 4; q++) acc[i][j][q] = 0.f;
            accX[i][j][0] = 0u; accX[i][j][1] = 0u;
        }

    load_stage(0);

    for (int s = 0; s < NS; s++) {
        CP_WAIT(0);
        __syncthreads();
        if (s + 1 < NS) load_stage(s + 1);

        const uint32_t stb = sbase + (s & 1) * STG;
        const uint32_t aA = stb + (wm * 32 + lrow) * RSTR + lhalf * 16;
        const uint32_t aB = stb + 2 * A_PL + (wn * 64 + lrow) * RSTR + lhalf * 16;

        #pragma unroll
        for (int kk = 0; kk < 4; kk++) {
            const uint32_t kb = kk * 32;
            uint32_t ah[2][4], al[2][4];
            ldm4(ah[0], aA + kb);
            ldm4(ah[1], aA + 16 * RSTR + kb);
            ldm4(al[0], aA + A_PL + kb);
            ldm4(al[1], aA + A_PL + 16 * RSTR + kb);
            #pragma unroll
            for (int j16 = 0; j16 < 4; j16++) {
                uint32_t th[4], tl[4];
                ldm4(th, aB + j16 * 16 * RSTR + kb);
                ldm4(tl, aB + B_PL + j16 * 16 * RSTR + kb);
                uint32_t bh0[2] = { th[0], th[2] };
                uint32_t bh1[2] = { th[1], th[3] };
                uint32_t bl0[2] = { tl[0], tl[2] };
                uint32_t bl1[2] = { tl[1], tl[3] };
                #pragma unroll
                for (int i = 0; i < 2; i++) {
                    mma_f32(acc[i][2*j16],   ah[i], bh0);
                    mma_f32(acc[i][2*j16+1], ah[i], bh1);
                    mma_f16(accX[i][2*j16],   al[i], bh0);
                    mma_f16(accX[i][2*j16],   ah[i], bl0);
                    mma_f16(accX[i][2*j16+1], al[i], bh1);
                    mma_f16(accX[i][2*j16+1], ah[i], bl1);
                }
            }
        }
    }

    // ---- epilogue ----
    const float* bias_v = bias + (size_t)view * NTOT;
    const int g4 = lane >> 2, t4 = lane & 3;

    #pragma unroll
    for (int i = 0; i < 2; i++) {
        #pragma unroll
        for (int j = 0; j < 8; j++) {
            const int row0 = grow + wm * 32 + i * 16 + g4;
            const int col  = gcol + wn * 64 + j * 8 + t4 * 2;
            const float b0 = __ldg(bias_v + col);
            const float b1 = __ldg(bias_v + col + 1);
            #pragma unroll
            for (int h = 0; h < 2; h++) {
                const int rw = row0 + h * 8;
                float2 xc = __half22float2(
                    *reinterpret_cast<const __half2*>(&accX[i][j][h]));
                float v0 = acc[i][j][h * 2 + 0] + xc.x + b0;
                float v1 = acc[i][j][h * 2 + 1] + xc.y + b1;
                const size_t go = (size_t)rw * NTOT + col;
                if (GELU) {
                    v0 = 0.5f * v0 * (1.0f + erff(v0 * 0.70710678118654752f));
                    v1 = 0.5f * v1 * (1.0f + erff(v1 * 0.70710678118654752f));
                    __half h0 = __float2half_rn(v0);
                    __half h1 = __float2half_rn(v1);
                    __half l0 = __float2half_rn(v0 - __half2float(h0));
                    __half l1 = __float2half_rn(v1 - __half2float(h1));
                    *(__half2*)(outH + go) = __halves2half2(h0, h1);
                    *(__half2*)(outL + go) = __halves2half2(l0, l1);
                } else {
                    float2 xv = *(const float2*)(xres + go);
                    float2 o;
                    o.x = xv.x + v0;
                    o.y = xv.y + v1;
                    *(float2*)(outp + go) = o;
                }
            }
        }
    }
}

// ---------------------------------------------------------------------------
// Launch
// ---------------------------------------------------------------------------
extern "C" void kernel_launch(void* const* d_in, const int* in_sizes, int n_in,
                              void* d_out, int out_size) {
    const float* x     = (const float*)d_in[0];
    const int*   idx   = (const int*)  d_in[1];
    const float* gamma = (const float*)d_in[2];
    const float* beta  = (const float*)d_in[3];
    const float* W1    = (const float*)d_in[4];
    const float* b1    = (const float*)d_in[5];
    const float* W2    = (const float*)d_in[6];
    const float* b2    = (const float*)d_in[7];
    float* out = (float*)d_out;

    void *p_xah, *p_xal, *p_hh, *p_hl, *p_w1h, *p_w1l, *p_w2h, *p_w2l;
    cudaGetSymbolAddress(&p_xah, g_xah);
    cudaGetSymbolAddress(&p_xal, g_xal);
    cudaGetSymbolAddress(&p_hh,  g_hh);
    cudaGetSymbolAddress(&p_hl,  g_hl);
    cudaGetSymbolAddress(&p_w1h, g_w1h);
    cudaGetSymbolAddress(&p_w1l, g_w1l);
    cudaGetSymbolAddress(&p_w2h, g_w2h);
    cudaGetSymbolAddress(&p_w2l, g_w2l);

    cudaFuncSetAttribute(gemm_mma<DIM, HID, true>,
                         cudaFuncAttributeMaxDynamicSharedMemorySize, SMEM_DYN);
    cudaFuncSetAttribute(gemm_mma<HID, DIM, false>,
                         cudaFuncAttributeMaxDynamicSharedMemorySize, SMEM_DYN);

    // 5 launches; gemm1 sits at launch index 3 so ncu -s 5 (with harness offset)
    // has a chance to capture it.
    decode_idx_kernel<<<1, 1>>>(idx);
    ln_kernel<<<ROWS, 256>>>(x, gamma, beta);
    wt_all_kernel<<<dim3(16384, 6), dim3(32, 8)>>>(W1, W2);

    gemm_mma<DIM, HID, true><<<(ROWS / 128) * (HID / 256), 512, SMEM_DYN>>>(
        (const __half*)p_xah, (const __half*)p_xal,
        (const __half*)p_w1h, (const __half*)p_w1l,
        b1, nullptr, nullptr,
        (__half*)p_hh, (__half*)p_hl);

    gemm_mma<HID, DIM, false><<<(ROWS / 128) * (DIM / 256), 512, SMEM_DYN>>>(
        (const __half*)p_hh, (const __half*)p_hl,
        (const __half*)p_w2h, (const __half*)p_w2l,
        b2, x, out, nullptr, nullptr);
}